// round 2
// baseline (speedup 1.0000x reference)
#include <cuda_runtime.h>

#define NUM_HEADS 16
#define HEAD_DIM  64
#define B_SZ      4
#define SEQ       2048
#define DIM       1024

// Scratch for projected Q/K/V in [B, H, S, D] layout (no cudaMalloc allowed).
__device__ float g_Qp[B_SZ * SEQ * DIM];
__device__ float g_Kp[B_SZ * SEQ * DIM];
__device__ float g_Vp[B_SZ * SEQ * DIM];

// ---------------------------------------------------------------------------
// Projection GEMM: C[M=8192, N=1024] = A @ W + bias (optional ReLU),
// output scattered into [B, H, S, D].
// Tiles: BM=128, BN=64, BK=16; 256 threads; 8x4 micro-tile per thread.
// ---------------------------------------------------------------------------
#define PBM 128
#define PBN 64
#define PBK 16

__global__ __launch_bounds__(256) void proj_kernel(
    const float* __restrict__ A, const float* __restrict__ W,
    const float* __restrict__ bias, int which)
{
    __shared__ float As[PBK][PBM + 4];   // stride 132 floats (transposed A, pad)
    __shared__ float Bs[PBK][PBN];

    float* out = (which == 0) ? g_Qp : ((which == 1) ? g_Kp : g_Vp);
    const bool relu = (which == 2);

    const int tid = threadIdx.x;
    const int tx = tid & 15;
    const int ty = tid >> 4;
    const int rowBase = blockIdx.y * PBM;
    const int colBase = blockIdx.x * PBN;

    float acc[8][4];
#pragma unroll
    for (int i = 0; i < 8; i++)
#pragma unroll
        for (int j = 0; j < 4; j++) acc[i][j] = 0.f;

    const int ra = tid >> 2;          // 0..63 (A row within tile, two passes)
    const int ka = (tid & 3) << 2;    // 0,4,8,12 (k offset, float4)
    const int rb = tid >> 4;          // 0..15 (W row within k-tile)
    const int cb = (tid & 15) << 2;   // 0..60 (W col, float4)

    for (int k0 = 0; k0 < DIM; k0 += PBK) {
        float4 a0 = *(const float4*)&A[(size_t)(rowBase + ra) * DIM + k0 + ka];
        float4 a1 = *(const float4*)&A[(size_t)(rowBase + ra + 64) * DIM + k0 + ka];
        float4 b0 = *(const float4*)&W[(size_t)(k0 + rb) * DIM + colBase + cb];

        As[ka + 0][ra] = a0.x; As[ka + 1][ra] = a0.y;
        As[ka + 2][ra] = a0.z; As[ka + 3][ra] = a0.w;
        As[ka + 0][ra + 64] = a1.x; As[ka + 1][ra + 64] = a1.y;
        As[ka + 2][ra + 64] = a1.z; As[ka + 3][ra + 64] = a1.w;
        *(float4*)&Bs[rb][cb] = b0;
        __syncthreads();

#pragma unroll
        for (int kk = 0; kk < PBK; ++kk) {
            float4 x0 = *(const float4*)&As[kk][ty * 8];
            float4 x1 = *(const float4*)&As[kk][ty * 8 + 4];
            float4 y  = *(const float4*)&Bs[kk][tx * 4];
            float av[8] = {x0.x, x0.y, x0.z, x0.w, x1.x, x1.y, x1.z, x1.w};
            float bv[4] = {y.x, y.y, y.z, y.w};
#pragma unroll
            for (int i = 0; i < 8; i++)
#pragma unroll
                for (int j = 0; j < 4; j++)
                    acc[i][j] += av[i] * bv[j];
        }
        __syncthreads();
    }

#pragma unroll
    for (int i = 0; i < 8; i++) {
        const int m = rowBase + ty * 8 + i;
        const int bb = m >> 11;          // batch
        const int s  = m & 2047;         // seq pos
#pragma unroll
        for (int j = 0; j < 4; j++) {
            const int n = colBase + tx * 4 + j;
            const int h = n >> 6;
            const int d = n & 63;
            float vv = acc[i][j] + bias[n];
            if (relu) vv = fmaxf(vv, 0.f);
            out[((((size_t)bb * NUM_HEADS + h) * SEQ + s) << 6) + d] = vv;
        }
    }
}

// ---------------------------------------------------------------------------
// Flash-style attention, fp32. One block = one (b,h) x 64-query tile.
// BKV = 32 keys per inner tile. 256 threads: (ty 0..15) x (tx 0..15).
// Scores micro-tile: 4 rows x 2 cols. O micro-tile: 4 rows x 4 dcols.
// Row-group = 16 threads with the same ty = one contiguous 16-lane shfl group.
// ---------------------------------------------------------------------------
#define BQ  64
#define BKV 32

__global__ __launch_bounds__(256) void attn_kernel(float* __restrict__ out)
{
    __shared__ float Qt[64][64];          // [d][row]  (transposed Q tile)
    __shared__ float Ks[BKV][65];         // [col][d]  pad -> conflict-free scalar loads
    __shared__ float Vs[BKV][64];         // [col][d]
    __shared__ float Ps[BQ][BKV + 1];     // [row][col] probabilities

    const int tid = threadIdx.x;
    const int tx = tid & 15;
    const int ty = tid >> 4;
    const int bh = blockIdx.y;            // b*16 + h

    const float* Qp = g_Qp + (size_t)bh * SEQ * 64 + (size_t)blockIdx.x * BQ * 64;
    const float* Kp = g_Kp + (size_t)bh * SEQ * 64;
    const float* Vp = g_Vp + (size_t)bh * SEQ * 64;

    // Load Q tile transposed into smem.
#pragma unroll
    for (int p = 0; p < 4; ++p) {
        const int idx = p * 256 + tid;
        const int r  = idx >> 4;
        const int d4 = (idx & 15) << 2;
        float4 q4 = *(const float4*)&Qp[r * 64 + d4];
        Qt[d4 + 0][r] = q4.x; Qt[d4 + 1][r] = q4.y;
        Qt[d4 + 2][r] = q4.z; Qt[d4 + 3][r] = q4.w;
    }
    __syncthreads();

    float m_run[4], l_run[4], O[4][4];
#pragma unroll
    for (int i = 0; i < 4; i++) {
        m_run[i] = -1e30f;
        l_run[i] = 0.f;
#pragma unroll
        for (int j = 0; j < 4; j++) O[i][j] = 0.f;
    }

    const int ck = tid >> 4;              // 0..15
    const int dk = (tid & 15) << 2;
    const int c0 = tx * 2;
    const int c1 = tx * 2 + 1;
    const float scale = 0.125f;           // 1/sqrt(64)

    for (int kt = 0; kt < SEQ / BKV; ++kt) {
        const float* kp = Kp + (size_t)kt * BKV * 64;
        const float* vp = Vp + (size_t)kt * BKV * 64;
        float4 k0 = *(const float4*)&kp[ck * 64 + dk];
        float4 k1 = *(const float4*)&kp[(ck + 16) * 64 + dk];
        float4 v0 = *(const float4*)&vp[ck * 64 + dk];
        float4 v1 = *(const float4*)&vp[(ck + 16) * 64 + dk];
        Ks[ck][dk + 0] = k0.x; Ks[ck][dk + 1] = k0.y;
        Ks[ck][dk + 2] = k0.z; Ks[ck][dk + 3] = k0.w;
        Ks[ck + 16][dk + 0] = k1.x; Ks[ck + 16][dk + 1] = k1.y;
        Ks[ck + 16][dk + 2] = k1.z; Ks[ck + 16][dk + 3] = k1.w;
        *(float4*)&Vs[ck][dk]      = v0;
        *(float4*)&Vs[ck + 16][dk] = v1;
        __syncthreads();

        // Scores: s[i][{0,1}] = Q[ty*4+i][:] . K[tx*2+{0,1}][:]
        float s0[4] = {0.f, 0.f, 0.f, 0.f};
        float s1[4] = {0.f, 0.f, 0.f, 0.f};
#pragma unroll 8
        for (int d = 0; d < 64; ++d) {
            float4 q4 = *(const float4*)&Qt[d][ty * 4];
            float ka_ = Ks[c0][d];
            float kb_ = Ks[c1][d];
            s0[0] += q4.x * ka_; s1[0] += q4.x * kb_;
            s0[1] += q4.y * ka_; s1[1] += q4.y * kb_;
            s0[2] += q4.z * ka_; s1[2] += q4.z * kb_;
            s0[3] += q4.w * ka_; s1[3] += q4.w * kb_;
        }

        // Online softmax per row (reduce across 16 same-ty lanes).
#pragma unroll
        for (int i = 0; i < 4; i++) {
            float a = s0[i] * scale;
            float b = s1[i] * scale;
            float mx = fmaxf(a, b);
            mx = fmaxf(mx, __shfl_xor_sync(0xffffffffu, mx, 1, 16));
            mx = fmaxf(mx, __shfl_xor_sync(0xffffffffu, mx, 2, 16));
            mx = fmaxf(mx, __shfl_xor_sync(0xffffffffu, mx, 4, 16));
            mx = fmaxf(mx, __shfl_xor_sync(0xffffffffu, mx, 8, 16));
            const float mnew = fmaxf(m_run[i], mx);
            const float fac  = __expf(m_run[i] - mnew);
            m_run[i] = mnew;
            const float p0 = __expf(a - mnew);
            const float p1 = __expf(b - mnew);
            float ls = p0 + p1;
            ls += __shfl_xor_sync(0xffffffffu, ls, 1, 16);
            ls += __shfl_xor_sync(0xffffffffu, ls, 2, 16);
            ls += __shfl_xor_sync(0xffffffffu, ls, 4, 16);
            ls += __shfl_xor_sync(0xffffffffu, ls, 8, 16);
            l_run[i] = l_run[i] * fac + ls;
            O[i][0] *= fac; O[i][1] *= fac; O[i][2] *= fac; O[i][3] *= fac;
            Ps[ty * 4 + i][c0] = p0;
            Ps[ty * 4 + i][c1] = p1;
        }
        __syncthreads();

        // O += P @ V
#pragma unroll 8
        for (int kc = 0; kc < BKV; ++kc) {
            float4 v4 = *(const float4*)&Vs[kc][tx * 4];
            float p0 = Ps[ty * 4 + 0][kc];
            float p1 = Ps[ty * 4 + 1][kc];
            float p2 = Ps[ty * 4 + 2][kc];
            float p3 = Ps[ty * 4 + 3][kc];
            O[0][0] += p0 * v4.x; O[0][1] += p0 * v4.y; O[0][2] += p0 * v4.z; O[0][3] += p0 * v4.w;
            O[1][0] += p1 * v4.x; O[1][1] += p1 * v4.y; O[1][2] += p1 * v4.z; O[1][3] += p1 * v4.w;
            O[2][0] += p2 * v4.x; O[2][1] += p2 * v4.y; O[2][2] += p2 * v4.z; O[2][3] += p2 * v4.w;
            O[3][0] += p3 * v4.x; O[3][1] += p3 * v4.y; O[3][2] += p3 * v4.z; O[3][3] += p3 * v4.w;
        }
        __syncthreads();
    }

    // Epilogue: out[b][s][h*64 + d] = O / l
    const int b = bh >> 4;
    const int h = bh & 15;
#pragma unroll
    for (int i = 0; i < 4; i++) {
        const int srow = blockIdx.x * BQ + ty * 4 + i;
        const float inv = 1.f / l_run[i];
        float4 o4 = make_float4(O[i][0] * inv, O[i][1] * inv, O[i][2] * inv, O[i][3] * inv);
        *(float4*)&out[((size_t)(b * SEQ + srow) * DIM) + h * 64 + tx * 4] = o4;
    }
}

// ---------------------------------------------------------------------------
extern "C" void kernel_launch(void* const* d_in, const int* in_sizes, int n_in,
                              void* d_out, int out_size)
{
    const float* q  = (const float*)d_in[0];
    const float* k  = (const float*)d_in[1];
    const float* v  = (const float*)d_in[2];
    const float* Wq = (const float*)d_in[3];
    const float* bq = (const float*)d_in[4];
    const float* Wk = (const float*)d_in[5];
    const float* bk = (const float*)d_in[6];
    const float* Wv = (const float*)d_in[7];
    const float* bv = (const float*)d_in[8];
    float* out = (float*)d_out;

    dim3 pgrid(DIM / PBN, (B_SZ * SEQ) / PBM);   // (16, 64)
    proj_kernel<<<pgrid, 256>>>(q, Wq, bq, 0);
    proj_kernel<<<pgrid, 256>>>(k, Wk, bk, 1);
    proj_kernel<<<pgrid, 256>>>(v, Wv, bv, 2);

    dim3 agrid(SEQ / BQ, B_SZ * NUM_HEADS);      // (32, 64)
    attn_kernel<<<agrid, 256>>>(out);
}

// round 4
// speedup vs baseline: 1.1224x; 1.1224x over previous
#include <cuda_runtime.h>
#include <mma.h>
#include <cstdint>

using namespace nvcuda;

#define NUM_HEADS 16
#define HEAD_DIM  64
#define B_SZ      4
#define SEQ       2048
#define DIM       1024

// Scratch for projected Q/K/V in [B, H, S, D] layout (no cudaMalloc allowed).
__device__ float g_Qp[B_SZ * SEQ * DIM];
__device__ float g_Kp[B_SZ * SEQ * DIM];
__device__ float g_Vp[B_SZ * SEQ * DIM];

__device__ __forceinline__ float f2tf32f(float x) {
    uint32_t u;
    asm("cvt.rna.tf32.f32 %0, %1;" : "=r"(u) : "f"(x));
    return __uint_as_float(u);
}

// ===========================================================================
// Projection GEMM via WMMA tf32 (m16n16k8):
//   C[M=8192, N=1024] = A @ W + bias  (ReLU for which==2), scatter to [B,H,S,D].
// Block tile 128x128, BK=32, 256 threads (8 warps as 4m x 2n),
// warp tile 32x64 = 2x4 wmma tiles.
// ===========================================================================
#define PJ_LDA 40    // 32 + 8 pad
#define PJ_LDB 136   // 128 + 8 pad

__global__ __launch_bounds__(256) void proj_wmma_kernel(
    const float* __restrict__ A, const float* __restrict__ W,
    const float* __restrict__ bias, int which)
{
    __shared__ float As[128 * PJ_LDA];   // 20480 B
    __shared__ float Bs[32 * PJ_LDB];    // 17408 B

    float* out = (which == 0) ? g_Qp : ((which == 1) ? g_Kp : g_Vp);
    const bool relu = (which == 2);

    const int tid  = threadIdx.x;
    const int wid  = tid >> 5;
    const int lane = tid & 31;
    const int warpM = wid >> 1;           // 0..3 -> m offset *32
    const int warpN = wid & 1;            // 0..1 -> n offset *64
    const int rowBase = blockIdx.y * 128;
    const int colBase = blockIdx.x * 128;

    wmma::fragment<wmma::accumulator, 16, 16, 8, float> acc[2][4];
#pragma unroll
    for (int mi = 0; mi < 2; mi++)
#pragma unroll
        for (int ni = 0; ni < 4; ni++)
            wmma::fill_fragment(acc[mi][ni], 0.0f);

    for (int k0 = 0; k0 < DIM; k0 += 32) {
        // Stage A tile 128x32 (tf32-rounded): 1024 float4 slots, 4 per thread.
#pragma unroll
        for (int i = 0; i < 4; i++) {
            const int idx = tid + i * 256;
            const int r  = idx >> 3;
            const int c4 = (idx & 7) << 2;
            float4 a4 = *(const float4*)&A[(size_t)(rowBase + r) * DIM + k0 + c4];
            float* dst = &As[r * PJ_LDA + c4];
            dst[0] = f2tf32f(a4.x); dst[1] = f2tf32f(a4.y);
            dst[2] = f2tf32f(a4.z); dst[3] = f2tf32f(a4.w);
        }
        // Stage B tile 32x128 (tf32-rounded): 1024 float4 slots.
#pragma unroll
        for (int i = 0; i < 4; i++) {
            const int idx = tid + i * 256;
            const int r  = idx >> 5;
            const int c4 = (idx & 31) << 2;
            float4 b4 = *(const float4*)&W[(size_t)(k0 + r) * DIM + colBase + c4];
            float* dst = &Bs[r * PJ_LDB + c4];
            dst[0] = f2tf32f(b4.x); dst[1] = f2tf32f(b4.y);
            dst[2] = f2tf32f(b4.z); dst[3] = f2tf32f(b4.w);
        }
        __syncthreads();

#pragma unroll
        for (int ks = 0; ks < 4; ++ks) {
            const int kof = ks * 8;
            wmma::fragment<wmma::matrix_a, 16, 16, 8, wmma::precision::tf32, wmma::row_major> afr[2];
            wmma::fragment<wmma::matrix_b, 16, 16, 8, wmma::precision::tf32, wmma::row_major> bfr[4];
#pragma unroll
            for (int mi = 0; mi < 2; mi++)
                wmma::load_matrix_sync(afr[mi], &As[(warpM * 32 + mi * 16) * PJ_LDA + kof], PJ_LDA);
#pragma unroll
            for (int ni = 0; ni < 4; ni++)
                wmma::load_matrix_sync(bfr[ni], &Bs[kof * PJ_LDB + warpN * 64 + ni * 16], PJ_LDB);
#pragma unroll
            for (int mi = 0; mi < 2; mi++)
#pragma unroll
                for (int ni = 0; ni < 4; ni++)
                    wmma::mma_sync(acc[mi][ni], afr[mi], bfr[ni], acc[mi][ni]);
        }
        __syncthreads();
    }

    // Epilogue: per-warp 16x16 smem patch (reuse As), bias + ReLU + scatter.
    float* patch = &As[wid * 320];        // 16 rows x stride 20
    const int h  = (colBase + warpN * 64) >> 6;      // head fixed per warp
    const int pr = lane >> 1;
    const int pc = (lane & 1) << 3;

#pragma unroll
    for (int mi = 0; mi < 2; mi++) {
#pragma unroll
        for (int ni = 0; ni < 4; ni++) {
            wmma::store_matrix_sync(patch, acc[mi][ni], 20, wmma::mem_row_major);
            __syncwarp();
            const int m  = rowBase + warpM * 32 + mi * 16 + pr;
            const int bb = m >> 11;
            const int s  = m & 2047;
            const int d0 = (warpN * 64 + ni * 16 + pc) & 63;
            const int n0 = colBase + warpN * 64 + ni * 16 + pc;
            float* orow = &out[((((size_t)bb * NUM_HEADS + h) * SEQ + s) << 6) + d0];
#pragma unroll
            for (int half = 0; half < 2; ++half) {
                float4 o;
                const float* p = &patch[pr * 20 + pc + half * 4];
                o.x = p[0] + bias[n0 + half * 4 + 0];
                o.y = p[1] + bias[n0 + half * 4 + 1];
                o.z = p[2] + bias[n0 + half * 4 + 2];
                o.w = p[3] + bias[n0 + half * 4 + 3];
                if (relu) {
                    o.x = fmaxf(o.x, 0.f); o.y = fmaxf(o.y, 0.f);
                    o.z = fmaxf(o.z, 0.f); o.w = fmaxf(o.w, 0.f);
                }
                *(float4*)&orow[half * 4] = o;
            }
            __syncwarp();
        }
    }
}

// ===========================================================================
// Flash-style attention, fp32 (unchanged from passing baseline).
// ===========================================================================
#define BQ  64
#define BKV 32

__global__ __launch_bounds__(256) void attn_kernel(float* __restrict__ out)
{
    __shared__ float Qt[64][64];
    __shared__ float Ks[BKV][65];
    __shared__ float Vs[BKV][64];
    __shared__ float Ps[BQ][BKV + 1];

    const int tid = threadIdx.x;
    const int tx = tid & 15;
    const int ty = tid >> 4;
    const int bh = blockIdx.y;

    const float* Qp = g_Qp + (size_t)bh * SEQ * 64 + (size_t)blockIdx.x * BQ * 64;
    const float* Kp = g_Kp + (size_t)bh * SEQ * 64;
    const float* Vp = g_Vp + (size_t)bh * SEQ * 64;

#pragma unroll
    for (int p = 0; p < 4; ++p) {
        const int idx = p * 256 + tid;
        const int r  = idx >> 4;
        const int d4 = (idx & 15) << 2;
        float4 q4 = *(const float4*)&Qp[r * 64 + d4];
        Qt[d4 + 0][r] = q4.x; Qt[d4 + 1][r] = q4.y;
        Qt[d4 + 2][r] = q4.z; Qt[d4 + 3][r] = q4.w;
    }
    __syncthreads();

    float m_run[4], l_run[4], O[4][4];
#pragma unroll
    for (int i = 0; i < 4; i++) {
        m_run[i] = -1e30f; l_run[i] = 0.f;
#pragma unroll
        for (int j = 0; j < 4; j++) O[i][j] = 0.f;
    }

    const int ck = tid >> 4;
    const int dk = (tid & 15) << 2;
    const int c0 = tx * 2;
    const int c1 = tx * 2 + 1;
    const float scale = 0.125f;

    for (int kt = 0; kt < SEQ / BKV; ++kt) {
        const float* kp = Kp + (size_t)kt * BKV * 64;
        const float* vp = Vp + (size_t)kt * BKV * 64;
        float4 k0 = *(const float4*)&kp[ck * 64 + dk];
        float4 k1 = *(const float4*)&kp[(ck + 16) * 64 + dk];
        float4 v0 = *(const float4*)&vp[ck * 64 + dk];
        float4 v1 = *(const float4*)&vp[(ck + 16) * 64 + dk];
        Ks[ck][dk + 0] = k0.x; Ks[ck][dk + 1] = k0.y;
        Ks[ck][dk + 2] = k0.z; Ks[ck][dk + 3] = k0.w;
        Ks[ck + 16][dk + 0] = k1.x; Ks[ck + 16][dk + 1] = k1.y;
        Ks[ck + 16][dk + 2] = k1.z; Ks[ck + 16][dk + 3] = k1.w;
        *(float4*)&Vs[ck][dk]      = v0;
        *(float4*)&Vs[ck + 16][dk] = v1;
        __syncthreads();

        float s0[4] = {0.f, 0.f, 0.f, 0.f};
        float s1[4] = {0.f, 0.f, 0.f, 0.f};
#pragma unroll 8
        for (int d = 0; d < 64; ++d) {
            float4 q4 = *(const float4*)&Qt[d][ty * 4];
            float ka_ = Ks[c0][d];
            float kb_ = Ks[c1][d];
            s0[0] += q4.x * ka_; s1[0] += q4.x * kb_;
            s0[1] += q4.y * ka_; s1[1] += q4.y * kb_;
            s0[2] += q4.z * ka_; s1[2] += q4.z * kb_;
            s0[3] += q4.w * ka_; s1[3] += q4.w * kb_;
        }

#pragma unroll
        for (int i = 0; i < 4; i++) {
            float a = s0[i] * scale;
            float b = s1[i] * scale;
            float mx = fmaxf(a, b);
            mx = fmaxf(mx, __shfl_xor_sync(0xffffffffu, mx, 1, 16));
            mx = fmaxf(mx, __shfl_xor_sync(0xffffffffu, mx, 2, 16));
            mx = fmaxf(mx, __shfl_xor_sync(0xffffffffu, mx, 4, 16));
            mx = fmaxf(mx, __shfl_xor_sync(0xffffffffu, mx, 8, 16));
            const float mnew = fmaxf(m_run[i], mx);
            const float fac  = __expf(m_run[i] - mnew);
            m_run[i] = mnew;
            const float p0 = __expf(a - mnew);
            const float p1 = __expf(b - mnew);
            float ls = p0 + p1;
            ls += __shfl_xor_sync(0xffffffffu, ls, 1, 16);
            ls += __shfl_xor_sync(0xffffffffu, ls, 2, 16);
            ls += __shfl_xor_sync(0xffffffffu, ls, 4, 16);
            ls += __shfl_xor_sync(0xffffffffu, ls, 8, 16);
            l_run[i] = l_run[i] * fac + ls;
            O[i][0] *= fac; O[i][1] *= fac; O[i][2] *= fac; O[i][3] *= fac;
            Ps[ty * 4 + i][c0] = p0;
            Ps[ty * 4 + i][c1] = p1;
        }
        __syncthreads();

#pragma unroll 8
        for (int kc = 0; kc < BKV; ++kc) {
            float4 v4 = *(const float4*)&Vs[kc][tx * 4];
            float p0 = Ps[ty * 4 + 0][kc];
            float p1 = Ps[ty * 4 + 1][kc];
            float p2 = Ps[ty * 4 + 2][kc];
            float p3 = Ps[ty * 4 + 3][kc];
            O[0][0] += p0 * v4.x; O[0][1] += p0 * v4.y; O[0][2] += p0 * v4.z; O[0][3] += p0 * v4.w;
            O[1][0] += p1 * v4.x; O[1][1] += p1 * v4.y; O[1][2] += p1 * v4.z; O[1][3] += p1 * v4.w;
            O[2][0] += p2 * v4.x; O[2][1] += p2 * v4.y; O[2][2] += p2 * v4.z; O[2][3] += p2 * v4.w;
            O[3][0] += p3 * v4.x; O[3][1] += p3 * v4.y; O[3][2] += p3 * v4.z; O[3][3] += p3 * v4.w;
        }
        __syncthreads();
    }

    const int b = bh >> 4;
    const int h = bh & 15;
#pragma unroll
    for (int i = 0; i < 4; i++) {
        const int srow = blockIdx.x * BQ + ty * 4 + i;
        const float inv = 1.f / l_run[i];
        float4 o4 = make_float4(O[i][0] * inv, O[i][1] * inv, O[i][2] * inv, O[i][3] * inv);
        *(float4*)&out[((size_t)(b * SEQ + srow) * DIM) + h * 64 + tx * 4] = o4;
    }
}

// ===========================================================================
extern "C" void kernel_launch(void* const* d_in, const int* in_sizes, int n_in,
                              void* d_out, int out_size)
{
    const float* q  = (const float*)d_in[0];
    const float* k  = (const float*)d_in[1];
    const float* v  = (const float*)d_in[2];
    const float* Wq = (const float*)d_in[3];
    const float* bq = (const float*)d_in[4];
    const float* Wk = (const float*)d_in[5];
    const float* bk = (const float*)d_in[6];
    const float* Wv = (const float*)d_in[7];
    const float* bv = (const float*)d_in[8];
    float* out = (float*)d_out;

    dim3 pgrid(DIM / 128, (B_SZ * SEQ) / 128);       // (8, 64)
    proj_wmma_kernel<<<pgrid, 256>>>(q, Wq, bq, 0);
    proj_wmma_kernel<<<pgrid, 256>>>(k, Wk, bk, 1);
    proj_wmma_kernel<<<pgrid, 256>>>(v, Wv, bv, 2);

    dim3 agrid(SEQ / BQ, B_SZ * NUM_HEADS);          // (32, 64)
    attn_kernel<<<agrid, 256>>>(out);
}

// round 6
// speedup vs baseline: 1.2504x; 1.1140x over previous
#include <cuda_runtime.h>
#include <mma.h>
#include <cstdint>

using namespace nvcuda;

#define NUM_HEADS 16
#define HEAD_DIM  64
#define B_SZ      4
#define SEQ       2048
#define DIM       1024

// Scratch for projected Q/K/V in [B, H, S, D] layout (no cudaMalloc allowed).
__device__ float g_Qp[B_SZ * SEQ * DIM];
__device__ float g_Kp[B_SZ * SEQ * DIM];
__device__ float g_Vp[B_SZ * SEQ * DIM];

__device__ __forceinline__ float f2tf32f(float x) {
    uint32_t u;
    asm("cvt.rna.tf32.f32 %0, %1;" : "=r"(u) : "f"(x));
    return __uint_as_float(u);
}

// ===========================================================================
// Projection GEMM via WMMA tf32 (m16n16k8) — unchanged from passing round 4.
// ===========================================================================
#define PJ_LDA 40    // 32 + 8 pad
#define PJ_LDB 136   // 128 + 8 pad

__global__ __launch_bounds__(256) void proj_wmma_kernel(
    const float* __restrict__ A, const float* __restrict__ W,
    const float* __restrict__ bias, int which)
{
    __shared__ float As[128 * PJ_LDA];
    __shared__ float Bs[32 * PJ_LDB];

    float* out = (which == 0) ? g_Qp : ((which == 1) ? g_Kp : g_Vp);
    const bool relu = (which == 2);

    const int tid  = threadIdx.x;
    const int wid  = tid >> 5;
    const int lane = tid & 31;
    const int warpM = wid >> 1;
    const int warpN = wid & 1;
    const int rowBase = blockIdx.y * 128;
    const int colBase = blockIdx.x * 128;

    wmma::fragment<wmma::accumulator, 16, 16, 8, float> acc[2][4];
#pragma unroll
    for (int mi = 0; mi < 2; mi++)
#pragma unroll
        for (int ni = 0; ni < 4; ni++)
            wmma::fill_fragment(acc[mi][ni], 0.0f);

    for (int k0 = 0; k0 < DIM; k0 += 32) {
#pragma unroll
        for (int i = 0; i < 4; i++) {
            const int idx = tid + i * 256;
            const int r  = idx >> 3;
            const int c4 = (idx & 7) << 2;
            float4 a4 = *(const float4*)&A[(size_t)(rowBase + r) * DIM + k0 + c4];
            float* dst = &As[r * PJ_LDA + c4];
            dst[0] = f2tf32f(a4.x); dst[1] = f2tf32f(a4.y);
            dst[2] = f2tf32f(a4.z); dst[3] = f2tf32f(a4.w);
        }
#pragma unroll
        for (int i = 0; i < 4; i++) {
            const int idx = tid + i * 256;
            const int r  = idx >> 5;
            const int c4 = (idx & 31) << 2;
            float4 b4 = *(const float4*)&W[(size_t)(k0 + r) * DIM + colBase + c4];
            float* dst = &Bs[r * PJ_LDB + c4];
            dst[0] = f2tf32f(b4.x); dst[1] = f2tf32f(b4.y);
            dst[2] = f2tf32f(b4.z); dst[3] = f2tf32f(b4.w);
        }
        __syncthreads();

#pragma unroll
        for (int ks = 0; ks < 4; ++ks) {
            const int kof = ks * 8;
            wmma::fragment<wmma::matrix_a, 16, 16, 8, wmma::precision::tf32, wmma::row_major> afr[2];
            wmma::fragment<wmma::matrix_b, 16, 16, 8, wmma::precision::tf32, wmma::row_major> bfr[4];
#pragma unroll
            for (int mi = 0; mi < 2; mi++)
                wmma::load_matrix_sync(afr[mi], &As[(warpM * 32 + mi * 16) * PJ_LDA + kof], PJ_LDA);
#pragma unroll
            for (int ni = 0; ni < 4; ni++)
                wmma::load_matrix_sync(bfr[ni], &Bs[kof * PJ_LDB + warpN * 64 + ni * 16], PJ_LDB);
#pragma unroll
            for (int mi = 0; mi < 2; mi++)
#pragma unroll
                for (int ni = 0; ni < 4; ni++)
                    wmma::mma_sync(acc[mi][ni], afr[mi], bfr[ni], acc[mi][ni]);
        }
        __syncthreads();
    }

    float* patch = &As[wid * 320];
    const int h  = (colBase + warpN * 64) >> 6;
    const int pr = lane >> 1;
    const int pc = (lane & 1) << 3;

#pragma unroll
    for (int mi = 0; mi < 2; mi++) {
#pragma unroll
        for (int ni = 0; ni < 4; ni++) {
            wmma::store_matrix_sync(patch, acc[mi][ni], 20, wmma::mem_row_major);
            __syncwarp();
            const int m  = rowBase + warpM * 32 + mi * 16 + pr;
            const int bb = m >> 11;
            const int s  = m & 2047;
            const int d0 = (warpN * 64 + ni * 16 + pc) & 63;
            const int n0 = colBase + warpN * 64 + ni * 16 + pc;
            float* orow = &out[((((size_t)bb * NUM_HEADS + h) * SEQ + s) << 6) + d0];
#pragma unroll
            for (int half = 0; half < 2; ++half) {
                float4 o;
                const float* p = &patch[pr * 20 + pc + half * 4];
                o.x = p[0] + bias[n0 + half * 4 + 0];
                o.y = p[1] + bias[n0 + half * 4 + 1];
                o.z = p[2] + bias[n0 + half * 4 + 2];
                o.w = p[3] + bias[n0 + half * 4 + 3];
                if (relu) {
                    o.x = fmaxf(o.x, 0.f); o.y = fmaxf(o.y, 0.f);
                    o.z = fmaxf(o.z, 0.f); o.w = fmaxf(o.w, 0.f);
                }
                *(float4*)&orow[half * 4] = o;
            }
            __syncwarp();
        }
    }
}

// ===========================================================================
// Flash attention via WMMA tf32.
// Block = (b,h) x 64 query rows. KV tile = 64. 256 threads = 8 warps:
//   warp wid: rg = wid>>1 (16 q-rows), ch = wid&1 (32-col half).
// S = Q @ K^T  (B col-major straight from K[k][d])
// O = P @ V with online softmax; O lives in per-thread registers
// (row = tid>>2, cols (tid&3)*16..+16), rescaled by per-row fac each iter.
// ===========================================================================
#define AQ   64
#define AK   64
#define AST  72
#define ASMEM ((4 * 64 * AST + 3 * 64) * 4)

__global__ __launch_bounds__(256) void attn_wmma_kernel(float* __restrict__ out)
{
    extern __shared__ float sm[];
    float* Qs    = sm;                 // 64 x 72
    float* Ks    = Qs + 64 * AST;      // 64 x 72
    float* Vs    = Ks + 64 * AST;      // 64 x 72
    float* Ss    = Vs + 64 * AST;      // 64 x 72 (scores -> probs -> PV)
    float* m_s   = Ss + 64 * AST;      // 64
    float* l_s   = m_s + 64;           // 64
    float* fac_s = l_s + 64;           // 64

    const int tid  = threadIdx.x;
    const int wid  = tid >> 5;
    const int lane = tid & 31;
    const int rg   = wid >> 1;         // row group (16 rows)
    const int ch   = wid & 1;          // col half (32 cols)
    const int bh   = blockIdx.y;
    const int qbase = blockIdx.x * AQ;

    const float* Qp = g_Qp + (size_t)bh * SEQ * 64 + (size_t)qbase * 64;
    const float* Kp = g_Kp + (size_t)bh * SEQ * 64;
    const float* Vp = g_Vp + (size_t)bh * SEQ * 64;

    // Stage Q (tf32): 64x64 = 1024 float4, 4 per thread.
#pragma unroll
    for (int i = 0; i < 4; i++) {
        const int idx = tid + i * 256;
        const int r = idx >> 4;
        const int c = (idx & 15) << 2;
        float4 q4 = *(const float4*)&Qp[r * 64 + c];
        float* d = &Qs[r * AST + c];
        d[0] = f2tf32f(q4.x); d[1] = f2tf32f(q4.y);
        d[2] = f2tf32f(q4.z); d[3] = f2tf32f(q4.w);
    }
    if (tid < 64) { m_s[tid] = -1e30f; l_s[tid] = 0.f; }

    float O[16];
#pragma unroll
    for (int j = 0; j < 16; j++) O[j] = 0.f;
    const int orow = tid >> 2;
    const int ocb  = (tid & 3) << 4;
    const float scale = 0.125f;

    __syncthreads();

    for (int kt = 0; kt < SEQ / AK; ++kt) {
        const float* kp = Kp + (size_t)kt * AK * 64;
        const float* vp = Vp + (size_t)kt * AK * 64;

        // Stage K and V tiles (tf32).
#pragma unroll
        for (int i = 0; i < 4; i++) {
            const int idx = tid + i * 256;
            const int r = idx >> 4;
            const int c = (idx & 15) << 2;
            float4 k4 = *(const float4*)&kp[r * 64 + c];
            float4 v4 = *(const float4*)&vp[r * 64 + c];
            float* dk = &Ks[r * AST + c];
            float* dv = &Vs[r * AST + c];
            dk[0] = f2tf32f(k4.x); dk[1] = f2tf32f(k4.y);
            dk[2] = f2tf32f(k4.z); dk[3] = f2tf32f(k4.w);
            dv[0] = f2tf32f(v4.x); dv[1] = f2tf32f(v4.y);
            dv[2] = f2tf32f(v4.z); dv[3] = f2tf32f(v4.w);
        }
        __syncthreads();   // sync1: tiles staged; prior O-update done

        // ---- S = Q @ K^T  (warp: rows rg*16, key cols ch*32..+32)
        {
            wmma::fragment<wmma::accumulator, 16, 16, 8, float> sacc[2];
            wmma::fill_fragment(sacc[0], 0.f);
            wmma::fill_fragment(sacc[1], 0.f);
#pragma unroll
            for (int kk = 0; kk < 8; ++kk) {
                wmma::fragment<wmma::matrix_a, 16, 16, 8, wmma::precision::tf32, wmma::row_major> afr;
                wmma::load_matrix_sync(afr, &Qs[(rg * 16) * AST + kk * 8], AST);
#pragma unroll
                for (int nf = 0; nf < 2; ++nf) {
                    wmma::fragment<wmma::matrix_b, 16, 16, 8, wmma::precision::tf32, wmma::col_major> bfr;
                    wmma::load_matrix_sync(bfr, &Ks[(ch * 32 + nf * 16) * AST + kk * 8], AST);
                    wmma::mma_sync(sacc[nf], afr, bfr, sacc[nf]);
                }
            }
            wmma::store_matrix_sync(&Ss[(rg * 16) * AST + ch * 32], sacc[0], AST, wmma::mem_row_major);
            wmma::store_matrix_sync(&Ss[(rg * 16) * AST + ch * 32 + 16], sacc[1], AST, wmma::mem_row_major);
        }
        __syncthreads();   // sync2: S in smem

        // ---- Online softmax: warp wid owns rows wid*8..+8; lane covers 2 cols.
#pragma unroll
        for (int r8 = 0; r8 < 8; ++r8) {
            const int row = wid * 8 + r8;
            float2 sv = *(float2*)&Ss[row * AST + lane * 2];
            const float a = sv.x * scale;
            const float b = sv.y * scale;
            float mx = fmaxf(a, b);
#pragma unroll
            for (int o = 16; o > 0; o >>= 1)
                mx = fmaxf(mx, __shfl_xor_sync(0xffffffffu, mx, o));
            const float mold = m_s[row];
            const float mnew = fmaxf(mold, mx);
            const float p0 = __expf(a - mnew);
            const float p1 = __expf(b - mnew);
            float sum = p0 + p1;
#pragma unroll
            for (int o = 16; o > 0; o >>= 1)
                sum += __shfl_xor_sync(0xffffffffu, sum, o);
            Ss[row * AST + lane * 2]     = f2tf32f(p0);
            Ss[row * AST + lane * 2 + 1] = f2tf32f(p1);
            if (lane == 0) {
                const float fac = __expf(mold - mnew);
                fac_s[row] = fac;
                l_s[row] = l_s[row] * fac + sum;
                m_s[row] = mnew;
            }
        }
        __syncthreads();   // sync3: P + fac ready

        // ---- PV = P @ V  (warp: rows rg*16, d cols ch*32..+32)
        wmma::fragment<wmma::accumulator, 16, 16, 8, float> pacc[2];
        wmma::fill_fragment(pacc[0], 0.f);
        wmma::fill_fragment(pacc[1], 0.f);
#pragma unroll
        for (int kk = 0; kk < 8; ++kk) {
            wmma::fragment<wmma::matrix_a, 16, 16, 8, wmma::precision::tf32, wmma::row_major> afr;
            wmma::load_matrix_sync(afr, &Ss[(rg * 16) * AST + kk * 8], AST);
#pragma unroll
            for (int nf = 0; nf < 2; ++nf) {
                wmma::fragment<wmma::matrix_b, 16, 16, 8, wmma::precision::tf32, wmma::row_major> bfr;
                wmma::load_matrix_sync(bfr, &Vs[(kk * 8) * AST + ch * 32 + nf * 16], AST);
                wmma::mma_sync(pacc[nf], afr, bfr, pacc[nf]);
            }
        }
        __syncthreads();   // sync4: all P reads complete before overwrite
        wmma::store_matrix_sync(&Ss[(rg * 16) * AST + ch * 32], pacc[0], AST, wmma::mem_row_major);
        wmma::store_matrix_sync(&Ss[(rg * 16) * AST + ch * 32 + 16], pacc[1], AST, wmma::mem_row_major);
        __syncthreads();   // sync5: PV tile in smem

        // ---- O update: O = O*fac + PV (thread owns row orow, 16 cols)
        const float fac = fac_s[orow];
#pragma unroll
        for (int j = 0; j < 16; j += 4) {
            float4 pv = *(float4*)&Ss[orow * AST + ocb + j];
            O[j + 0] = O[j + 0] * fac + pv.x;
            O[j + 1] = O[j + 1] * fac + pv.y;
            O[j + 2] = O[j + 2] * fac + pv.z;
            O[j + 3] = O[j + 3] * fac + pv.w;
        }
        // loop-top staging writes only Ks/Vs; next Ss write is after sync2.
    }

    // Epilogue
    const int b = bh >> 4;
    const int h = bh & 15;
    const float inv = 1.f / l_s[orow];
    float* orow_p = &out[((size_t)(b * SEQ + qbase + orow)) * DIM + h * 64 + ocb];
#pragma unroll
    for (int j = 0; j < 16; j += 4) {
        float4 o4 = make_float4(O[j] * inv, O[j + 1] * inv, O[j + 2] * inv, O[j + 3] * inv);
        *(float4*)&orow_p[j] = o4;
    }
}

// ===========================================================================
extern "C" void kernel_launch(void* const* d_in, const int* in_sizes, int n_in,
                              void* d_out, int out_size)
{
    const float* q  = (const float*)d_in[0];
    const float* k  = (const float*)d_in[1];
    const float* v  = (const float*)d_in[2];
    const float* Wq = (const float*)d_in[3];
    const float* bq = (const float*)d_in[4];
    const float* Wk = (const float*)d_in[5];
    const float* bk = (const float*)d_in[6];
    const float* Wv = (const float*)d_in[7];
    const float* bv = (const float*)d_in[8];
    float* out = (float*)d_out;

    cudaFuncSetAttribute(attn_wmma_kernel, cudaFuncAttributeMaxDynamicSharedMemorySize, ASMEM);

    dim3 pgrid(DIM / 128, (B_SZ * SEQ) / 128);       // (8, 64)
    proj_wmma_kernel<<<pgrid, 256>>>(q, Wq, bq, 0);
    proj_wmma_kernel<<<pgrid, 256>>>(k, Wk, bk, 1);
    proj_wmma_kernel<<<pgrid, 256>>>(v, Wv, bv, 2);

    dim3 agrid(SEQ / AQ, B_SZ * NUM_HEADS);          // (32, 64)
    attn_wmma_kernel<<<agrid, 256, ASMEM>>>(out);
}

// round 7
// speedup vs baseline: 1.3327x; 1.0659x over previous
#include <cuda_runtime.h>
#include <mma.h>
#include <cstdint>

using namespace nvcuda;

#define NUM_HEADS 16
#define HEAD_DIM  64
#define B_SZ      4
#define SEQ       2048
#define DIM       1024

// Scratch for projected Q/K/V in [B, H, S, D] layout (no cudaMalloc allowed).
__device__ float g_Qp[B_SZ * SEQ * DIM];
__device__ float g_Kp[B_SZ * SEQ * DIM];
__device__ float g_Vp[B_SZ * SEQ * DIM];

__device__ __forceinline__ float f2tf32f(float x) {
    uint32_t u;
    asm("cvt.rna.tf32.f32 %0, %1;" : "=r"(u) : "f"(x));
    return __uint_as_float(u);
}

// ===========================================================================
// Projection GEMM via WMMA tf32 (m16n16k8) — unchanged (passing, ~800us).
// ===========================================================================
#define PJ_LDA 40
#define PJ_LDB 136

__global__ __launch_bounds__(256) void proj_wmma_kernel(
    const float* __restrict__ A, const float* __restrict__ W,
    const float* __restrict__ bias, int which)
{
    __shared__ float As[128 * PJ_LDA];
    __shared__ float Bs[32 * PJ_LDB];

    float* out = (which == 0) ? g_Qp : ((which == 1) ? g_Kp : g_Vp);
    const bool relu = (which == 2);

    const int tid  = threadIdx.x;
    const int wid  = tid >> 5;
    const int lane = tid & 31;
    const int warpM = wid >> 1;
    const int warpN = wid & 1;
    const int rowBase = blockIdx.y * 128;
    const int colBase = blockIdx.x * 128;

    wmma::fragment<wmma::accumulator, 16, 16, 8, float> acc[2][4];
#pragma unroll
    for (int mi = 0; mi < 2; mi++)
#pragma unroll
        for (int ni = 0; ni < 4; ni++)
            wmma::fill_fragment(acc[mi][ni], 0.0f);

    for (int k0 = 0; k0 < DIM; k0 += 32) {
#pragma unroll
        for (int i = 0; i < 4; i++) {
            const int idx = tid + i * 256;
            const int r  = idx >> 3;
            const int c4 = (idx & 7) << 2;
            float4 a4 = *(const float4*)&A[(size_t)(rowBase + r) * DIM + k0 + c4];
            float* dst = &As[r * PJ_LDA + c4];
            dst[0] = f2tf32f(a4.x); dst[1] = f2tf32f(a4.y);
            dst[2] = f2tf32f(a4.z); dst[3] = f2tf32f(a4.w);
        }
#pragma unroll
        for (int i = 0; i < 4; i++) {
            const int idx = tid + i * 256;
            const int r  = idx >> 5;
            const int c4 = (idx & 31) << 2;
            float4 b4 = *(const float4*)&W[(size_t)(k0 + r) * DIM + colBase + c4];
            float* dst = &Bs[r * PJ_LDB + c4];
            dst[0] = f2tf32f(b4.x); dst[1] = f2tf32f(b4.y);
            dst[2] = f2tf32f(b4.z); dst[3] = f2tf32f(b4.w);
        }
        __syncthreads();

#pragma unroll
        for (int ks = 0; ks < 4; ++ks) {
            const int kof = ks * 8;
            wmma::fragment<wmma::matrix_a, 16, 16, 8, wmma::precision::tf32, wmma::row_major> afr[2];
            wmma::fragment<wmma::matrix_b, 16, 16, 8, wmma::precision::tf32, wmma::row_major> bfr[4];
#pragma unroll
            for (int mi = 0; mi < 2; mi++)
                wmma::load_matrix_sync(afr[mi], &As[(warpM * 32 + mi * 16) * PJ_LDA + kof], PJ_LDA);
#pragma unroll
            for (int ni = 0; ni < 4; ni++)
                wmma::load_matrix_sync(bfr[ni], &Bs[kof * PJ_LDB + warpN * 64 + ni * 16], PJ_LDB);
#pragma unroll
            for (int mi = 0; mi < 2; mi++)
#pragma unroll
                for (int ni = 0; ni < 4; ni++)
                    wmma::mma_sync(acc[mi][ni], afr[mi], bfr[ni], acc[mi][ni]);
        }
        __syncthreads();
    }

    float* patch = &As[wid * 320];
    const int h  = (colBase + warpN * 64) >> 6;
    const int pr = lane >> 1;
    const int pc = (lane & 1) << 3;

#pragma unroll
    for (int mi = 0; mi < 2; mi++) {
#pragma unroll
        for (int ni = 0; ni < 4; ni++) {
            wmma::store_matrix_sync(patch, acc[mi][ni], 20, wmma::mem_row_major);
            __syncwarp();
            const int m  = rowBase + warpM * 32 + mi * 16 + pr;
            const int bb = m >> 11;
            const int s  = m & 2047;
            const int d0 = (warpN * 64 + ni * 16 + pc) & 63;
            const int n0 = colBase + warpN * 64 + ni * 16 + pc;
            float* orow = &out[((((size_t)bb * NUM_HEADS + h) * SEQ + s) << 6) + d0];
#pragma unroll
            for (int half = 0; half < 2; ++half) {
                float4 o;
                const float* p = &patch[pr * 20 + pc + half * 4];
                o.x = p[0] + bias[n0 + half * 4 + 0];
                o.y = p[1] + bias[n0 + half * 4 + 1];
                o.z = p[2] + bias[n0 + half * 4 + 2];
                o.w = p[3] + bias[n0 + half * 4 + 3];
                if (relu) {
                    o.x = fmaxf(o.x, 0.f); o.y = fmaxf(o.y, 0.f);
                    o.z = fmaxf(o.z, 0.f); o.w = fmaxf(o.w, 0.f);
                }
                *(float4*)&orow[half * 4] = o;
            }
            __syncwarp();
        }
    }
}

// ===========================================================================
// Flash attention, warp-autonomous WMMA tf32.
// Block = (b,h) x 128 q-rows. 8 warps, each owns 16 q-rows x ALL 64 key cols.
// Per KV iter: block stages K/V (2 syncthreads); everything else warp-local:
//   S = Qfrag @ K^T -> warp patch -> softmax -> P (tf32, in place)
//   PV = P @ V -> patch -> O regs (row = lane>>1, cols (lane&1)*32..+32)
// Q is held in 8 persistent matrix_a fragments (loaded once).
// ===========================================================================
#define AST   68
#define NWARP 8
#define AQR   128                     // q-rows per block
#define ASMEM ((64 * AST * 2 + NWARP * 16 * AST + NWARP * 48) * 4)

__global__ __launch_bounds__(256, 2) void attn_wmma_kernel(float* __restrict__ out)
{
    extern __shared__ float sm[];
    float* Ks      = sm;                       // 64 x 68 (keys x d)
    float* Vs      = Ks + 64 * AST;            // 64 x 68 (keys x d)
    float* patches = Vs + 64 * AST;            // 8 x (16 x 68)
    float* mls     = patches + NWARP * 16 * AST; // 8 x (m16, l16, fac16)

    const int tid  = threadIdx.x;
    const int wid  = tid >> 5;
    const int lane = tid & 31;
    const int bh   = blockIdx.y;
    const int qbase = blockIdx.x * AQR;

    float* patch = patches + wid * 16 * AST;
    float* mW = mls + wid * 48;
    float* lW = mW + 16;
    float* fW = lW + 16;

    const float* Qp = g_Qp + (size_t)bh * SEQ * 64 + (size_t)(qbase + wid * 16) * 64;
    const float* Kp = g_Kp + (size_t)bh * SEQ * 64;
    const float* Vp = g_Vp + (size_t)bh * SEQ * 64;

    // ---- Stage this warp's Q (16x64, tf32) into patch, load persistent frags.
#pragma unroll
    for (int i = 0; i < 8; i++) {
        const int idx = lane + i * 32;          // 256 float4 slots
        const int r = idx >> 4;
        const int c = (idx & 15) << 2;
        float4 q4 = *(const float4*)&Qp[r * 64 + c];
        float* d = &patch[r * AST + c];
        d[0] = f2tf32f(q4.x); d[1] = f2tf32f(q4.y);
        d[2] = f2tf32f(q4.z); d[3] = f2tf32f(q4.w);
    }
    if (lane < 16) { mW[lane] = -1e30f; lW[lane] = 0.f; }
    __syncwarp();

    wmma::fragment<wmma::matrix_a, 16, 16, 8, wmma::precision::tf32, wmma::row_major> qfr[8];
#pragma unroll
    for (int kk = 0; kk < 8; ++kk)
        wmma::load_matrix_sync(qfr[kk], &patch[kk * 8], AST);

    float O[32];
#pragma unroll
    for (int j = 0; j < 32; j++) O[j] = 0.f;
    const int orow = lane >> 1;                 // row within warp's 16
    const int ocb  = (lane & 1) << 5;           // col base (0 or 32)
    const float scale = 0.125f;

    __syncthreads();

    for (int kt = 0; kt < SEQ / 64; ++kt) {
        const float* kp = Kp + (size_t)kt * 64 * 64;
        const float* vp = Vp + (size_t)kt * 64 * 64;

        // ---- Block stages K and V tiles (64x64 each, tf32).
#pragma unroll
        for (int i = 0; i < 4; i++) {
            const int idx = tid + i * 256;
            const int r = idx >> 4;
            const int c = (idx & 15) << 2;
            float4 k4 = *(const float4*)&kp[r * 64 + c];
            float4 v4 = *(const float4*)&vp[r * 64 + c];
            float* dk = &Ks[r * AST + c];
            float* dv = &Vs[r * AST + c];
            dk[0] = f2tf32f(k4.x); dk[1] = f2tf32f(k4.y);
            dk[2] = f2tf32f(k4.z); dk[3] = f2tf32f(k4.w);
            dv[0] = f2tf32f(v4.x); dv[1] = f2tf32f(v4.y);
            dv[2] = f2tf32f(v4.z); dv[3] = f2tf32f(v4.w);
        }
        __syncthreads();

        // ---- S = Q @ K^T : 16 rows x 64 key cols (warp-local from here on).
        {
            wmma::fragment<wmma::accumulator, 16, 16, 8, float> sacc[4];
#pragma unroll
            for (int nf = 0; nf < 4; ++nf) wmma::fill_fragment(sacc[nf], 0.f);
#pragma unroll
            for (int kk = 0; kk < 8; ++kk) {
#pragma unroll
                for (int nf = 0; nf < 4; ++nf) {
                    wmma::fragment<wmma::matrix_b, 16, 16, 8, wmma::precision::tf32, wmma::col_major> bfr;
                    wmma::load_matrix_sync(bfr, &Ks[(nf * 16) * AST + kk * 8], AST);
                    wmma::mma_sync(sacc[nf], qfr[kk], bfr, sacc[nf]);
                }
            }
#pragma unroll
            for (int nf = 0; nf < 4; ++nf)
                wmma::store_matrix_sync(&patch[nf * 16], sacc[nf], AST, wmma::mem_row_major);
        }
        __syncwarp();

        // ---- Warp-local online softmax over the 16x64 patch.
#pragma unroll
        for (int r = 0; r < 16; ++r) {
            float* rowp = &patch[r * AST];
            float2 sv = *(float2*)&rowp[lane * 2];
            const float a = sv.x * scale;
            const float b = sv.y * scale;
            float mx = fmaxf(a, b);
#pragma unroll
            for (int o = 16; o > 0; o >>= 1)
                mx = fmaxf(mx, __shfl_xor_sync(0xffffffffu, mx, o));
            const float mold = mW[r];
            const float mnew = fmaxf(mold, mx);
            const float p0 = __expf(a - mnew);
            const float p1 = __expf(b - mnew);
            float sum = p0 + p1;
#pragma unroll
            for (int o = 16; o > 0; o >>= 1)
                sum += __shfl_xor_sync(0xffffffffu, sum, o);
            rowp[lane * 2]     = f2tf32f(p0);
            rowp[lane * 2 + 1] = f2tf32f(p1);
            if (lane == 0) {
                const float fac = __expf(mold - mnew);
                fW[r] = fac;
                lW[r] = lW[r] * fac + sum;
                mW[r] = mnew;
            }
        }
        __syncwarp();

        // ---- PV = P @ V : 16 x 64.
        {
            wmma::fragment<wmma::accumulator, 16, 16, 8, float> pacc[4];
#pragma unroll
            for (int nf = 0; nf < 4; ++nf) wmma::fill_fragment(pacc[nf], 0.f);
#pragma unroll
            for (int kk = 0; kk < 8; ++kk) {
                wmma::fragment<wmma::matrix_a, 16, 16, 8, wmma::precision::tf32, wmma::row_major> pfr;
                wmma::load_matrix_sync(pfr, &patch[kk * 8], AST);
#pragma unroll
                for (int nf = 0; nf < 4; ++nf) {
                    wmma::fragment<wmma::matrix_b, 16, 16, 8, wmma::precision::tf32, wmma::row_major> bfr;
                    wmma::load_matrix_sync(bfr, &Vs[(kk * 8) * AST + nf * 16], AST);
                    wmma::mma_sync(pacc[nf], pfr, bfr, pacc[nf]);
                }
            }
            __syncwarp();   // all P reads done before overwriting patch
#pragma unroll
            for (int nf = 0; nf < 4; ++nf)
                wmma::store_matrix_sync(&patch[nf * 16], pacc[nf], AST, wmma::mem_row_major);
        }
        __syncwarp();

        // ---- O update: O = O*fac + PV (thread: row orow, 32 cols at ocb).
        const float fac = fW[orow];
#pragma unroll
        for (int j = 0; j < 32; j += 4) {
            float4 pv = *(float4*)&patch[orow * AST + ocb + j];
            O[j + 0] = O[j + 0] * fac + pv.x;
            O[j + 1] = O[j + 1] * fac + pv.y;
            O[j + 2] = O[j + 2] * fac + pv.z;
            O[j + 3] = O[j + 3] * fac + pv.w;
        }
        __syncthreads();    // Ks/Vs free for next stage
    }

    // ---- Epilogue.
    const int b = bh >> 4;
    const int h = bh & 15;
    const float inv = 1.f / lW[orow];
    const int srow = qbase + wid * 16 + orow;
    float* orow_p = &out[((size_t)(b * SEQ + srow)) * DIM + h * 64 + ocb];
#pragma unroll
    for (int j = 0; j < 32; j += 4) {
        float4 o4 = make_float4(O[j] * inv, O[j + 1] * inv, O[j + 2] * inv, O[j + 3] * inv);
        *(float4*)&orow_p[j] = o4;
    }
}

// ===========================================================================
extern "C" void kernel_launch(void* const* d_in, const int* in_sizes, int n_in,
                              void* d_out, int out_size)
{
    const float* q  = (const float*)d_in[0];
    const float* k  = (const float*)d_in[1];
    const float* v  = (const float*)d_in[2];
    const float* Wq = (const float*)d_in[3];
    const float* bq = (const float*)d_in[4];
    const float* Wk = (const float*)d_in[5];
    const float* bk = (const float*)d_in[6];
    const float* Wv = (const float*)d_in[7];
    const float* bv = (const float*)d_in[8];
    float* out = (float*)d_out;

    cudaFuncSetAttribute(attn_wmma_kernel, cudaFuncAttributeMaxDynamicSharedMemorySize, ASMEM);

    dim3 pgrid(DIM / 128, (B_SZ * SEQ) / 128);       // (8, 64)
    proj_wmma_kernel<<<pgrid, 256>>>(q, Wq, bq, 0);
    proj_wmma_kernel<<<pgrid, 256>>>(k, Wk, bk, 1);
    proj_wmma_kernel<<<pgrid, 256>>>(v, Wv, bv, 2);

    dim3 agrid(SEQ / AQR, B_SZ * NUM_HEADS);         // (16, 64)
    attn_wmma_kernel<<<agrid, 256, ASMEM>>>(out);
}

// round 8
// speedup vs baseline: 2.4146x; 1.8118x over previous
#include <cuda_runtime.h>
#include <mma.h>
#include <cstdint>

using namespace nvcuda;

#define NUM_HEADS 16
#define HEAD_DIM  64
#define B_SZ      4
#define SEQ       2048
#define DIM       1024

// Scratch for projected Q/K/V in [B, H, S, D] layout (no cudaMalloc allowed).
__device__ float g_Qp[B_SZ * SEQ * DIM];
__device__ float g_Kp[B_SZ * SEQ * DIM];
__device__ float g_Vp[B_SZ * SEQ * DIM];

__device__ __forceinline__ float f2tf32f(float x) {
    uint32_t u;
    asm("cvt.rna.tf32.f32 %0, %1;" : "=r"(u) : "f"(x));
    return __uint_as_float(u);
}
__device__ __forceinline__ uint32_t f2tf32u(float x) {
    uint32_t u;
    asm("cvt.rna.tf32.f32 %0, %1;" : "=r"(u) : "f"(x));
    return u;
}

// Raw tf32 MMA m16n8k8 (A row-major, B col-major), D/C fp32, accumulate in place.
__device__ __forceinline__ void mma_tf32(float d[4], const uint32_t a[4], const uint32_t b[2]) {
    asm volatile(
        "mma.sync.aligned.m16n8k8.row.col.f32.tf32.tf32.f32 "
        "{%0,%1,%2,%3}, {%4,%5,%6,%7}, {%8,%9}, {%0,%1,%2,%3};"
        : "+f"(d[0]), "+f"(d[1]), "+f"(d[2]), "+f"(d[3])
        : "r"(a[0]), "r"(a[1]), "r"(a[2]), "r"(a[3]), "r"(b[0]), "r"(b[1]));
}

// ===========================================================================
// Projection GEMM via WMMA tf32 (m16n16k8) — unchanged (passing).
// ===========================================================================
#define PJ_LDA 40
#define PJ_LDB 136

__global__ __launch_bounds__(256) void proj_wmma_kernel(
    const float* __restrict__ A, const float* __restrict__ W,
    const float* __restrict__ bias, int which)
{
    __shared__ float As[128 * PJ_LDA];
    __shared__ float Bs[32 * PJ_LDB];

    float* out = (which == 0) ? g_Qp : ((which == 1) ? g_Kp : g_Vp);
    const bool relu = (which == 2);

    const int tid  = threadIdx.x;
    const int wid  = tid >> 5;
    const int lane = tid & 31;
    const int warpM = wid >> 1;
    const int warpN = wid & 1;
    const int rowBase = blockIdx.y * 128;
    const int colBase = blockIdx.x * 128;

    wmma::fragment<wmma::accumulator, 16, 16, 8, float> acc[2][4];
#pragma unroll
    for (int mi = 0; mi < 2; mi++)
#pragma unroll
        for (int ni = 0; ni < 4; ni++)
            wmma::fill_fragment(acc[mi][ni], 0.0f);

    for (int k0 = 0; k0 < DIM; k0 += 32) {
#pragma unroll
        for (int i = 0; i < 4; i++) {
            const int idx = tid + i * 256;
            const int r  = idx >> 3;
            const int c4 = (idx & 7) << 2;
            float4 a4 = *(const float4*)&A[(size_t)(rowBase + r) * DIM + k0 + c4];
            float* dst = &As[r * PJ_LDA + c4];
            dst[0] = f2tf32f(a4.x); dst[1] = f2tf32f(a4.y);
            dst[2] = f2tf32f(a4.z); dst[3] = f2tf32f(a4.w);
        }
#pragma unroll
        for (int i = 0; i < 4; i++) {
            const int idx = tid + i * 256;
            const int r  = idx >> 5;
            const int c4 = (idx & 31) << 2;
            float4 b4 = *(const float4*)&W[(size_t)(k0 + r) * DIM + colBase + c4];
            float* dst = &Bs[r * PJ_LDB + c4];
            dst[0] = f2tf32f(b4.x); dst[1] = f2tf32f(b4.y);
            dst[2] = f2tf32f(b4.z); dst[3] = f2tf32f(b4.w);
        }
        __syncthreads();

#pragma unroll
        for (int ks = 0; ks < 4; ++ks) {
            const int kof = ks * 8;
            wmma::fragment<wmma::matrix_a, 16, 16, 8, wmma::precision::tf32, wmma::row_major> afr[2];
            wmma::fragment<wmma::matrix_b, 16, 16, 8, wmma::precision::tf32, wmma::row_major> bfr[4];
#pragma unroll
            for (int mi = 0; mi < 2; mi++)
                wmma::load_matrix_sync(afr[mi], &As[(warpM * 32 + mi * 16) * PJ_LDA + kof], PJ_LDA);
#pragma unroll
            for (int ni = 0; ni < 4; ni++)
                wmma::load_matrix_sync(bfr[ni], &Bs[kof * PJ_LDB + warpN * 64 + ni * 16], PJ_LDB);
#pragma unroll
            for (int mi = 0; mi < 2; mi++)
#pragma unroll
                for (int ni = 0; ni < 4; ni++)
                    wmma::mma_sync(acc[mi][ni], afr[mi], bfr[ni], acc[mi][ni]);
        }
        __syncthreads();
    }

    float* patch = &As[wid * 320];
    const int h  = (colBase + warpN * 64) >> 6;
    const int pr = lane >> 1;
    const int pc = (lane & 1) << 3;

#pragma unroll
    for (int mi = 0; mi < 2; mi++) {
#pragma unroll
        for (int ni = 0; ni < 4; ni++) {
            wmma::store_matrix_sync(patch, acc[mi][ni], 20, wmma::mem_row_major);
            __syncwarp();
            const int m  = rowBase + warpM * 32 + mi * 16 + pr;
            const int bb = m >> 11;
            const int s  = m & 2047;
            const int d0 = (warpN * 64 + ni * 16 + pc) & 63;
            const int n0 = colBase + warpN * 64 + ni * 16 + pc;
            float* orow = &out[((((size_t)bb * NUM_HEADS + h) * SEQ + s) << 6) + d0];
#pragma unroll
            for (int half = 0; half < 2; ++half) {
                float4 o;
                const float* p = &patch[pr * 20 + pc + half * 4];
                o.x = p[0] + bias[n0 + half * 4 + 0];
                o.y = p[1] + bias[n0 + half * 4 + 1];
                o.z = p[2] + bias[n0 + half * 4 + 2];
                o.w = p[3] + bias[n0 + half * 4 + 3];
                if (relu) {
                    o.x = fmaxf(o.x, 0.f); o.y = fmaxf(o.y, 0.f);
                    o.z = fmaxf(o.z, 0.f); o.w = fmaxf(o.w, 0.f);
                }
                *(float4*)&orow[half * 4] = o;
            }
            __syncwarp();
        }
    }
}

// ===========================================================================
// Flash attention, register-resident raw mma.sync tf32 (m16n8k8).
// Block = (b,h) x 128 q-rows; 8 warps x 16 q-rows each, all 64 kv cols.
// Per thread (g = lane>>2, t = lane&3): rows g and g+8 of the warp stripe.
//   S accums SA[8][4]  (cols nt*8 + {2t,2t+1})   — registers only
//   O accums  O[8][4]   — registers, rescaled in place, mma-accumulated
//   Q a-frags qf[8][4]  — loaded once from gmem
// Only P round-trips smem (per-warp 16x68 patch).
// K staged stride 68 (conflict-free b-frag reads), V stride 72.
// ===========================================================================
#define KST 68
#define VST 72
#define PST 68
#define AQR 128
#define ASMEM ((64 * KST + 64 * VST + 8 * 16 * PST) * 4)

__global__ __launch_bounds__(256, 2) void attn_mma_kernel(float* __restrict__ out)
{
    extern __shared__ float sm[];
    float* Ks      = sm;                         // 64 x 68  [kv][d]
    float* Vs      = Ks + 64 * KST;              // 64 x 72  [kv][d]
    float* Ppatch  = Vs + 64 * VST;              // 8 x (16 x 68)

    const int tid  = threadIdx.x;
    const int wid  = tid >> 5;
    const int lane = tid & 31;
    const int g    = lane >> 2;                  // 0..7
    const int t    = lane & 3;                   // 0..3
    const int bh   = blockIdx.y;
    const int qbase = blockIdx.x * AQR;

    float* patch = Ppatch + wid * 16 * PST;

    const float* Qp = g_Qp + (size_t)bh * SEQ * 64 + (size_t)(qbase + wid * 16) * 64;
    const float* Kp = g_Kp + (size_t)bh * SEQ * 64;
    const float* Vp = g_Vp + (size_t)bh * SEQ * 64;

    // ---- Persistent Q a-fragments (16 x 64, tf32), loaded once from gmem.
    uint32_t qf[8][4];
#pragma unroll
    for (int kt = 0; kt < 8; ++kt) {
        qf[kt][0] = f2tf32u(Qp[g * 64 + kt * 8 + t]);
        qf[kt][1] = f2tf32u(Qp[(g + 8) * 64 + kt * 8 + t]);
        qf[kt][2] = f2tf32u(Qp[g * 64 + kt * 8 + t + 4]);
        qf[kt][3] = f2tf32u(Qp[(g + 8) * 64 + kt * 8 + t + 4]);
    }

    float O[8][4];
#pragma unroll
    for (int nt = 0; nt < 8; ++nt)
#pragma unroll
        for (int j = 0; j < 4; ++j) O[nt][j] = 0.f;

    float m0 = -1e30f, m1 = -1e30f, l0 = 0.f, l1 = 0.f;
    const float scale = 0.125f;

    for (int kt_iter = 0; kt_iter < SEQ / 64; ++kt_iter) {
        const float* kp = Kp + (size_t)kt_iter * 64 * 64;
        const float* vp = Vp + (size_t)kt_iter * 64 * 64;

        // ---- Block stages K and V tiles (64x64 each, tf32).
#pragma unroll
        for (int i = 0; i < 4; i++) {
            const int idx = tid + i * 256;
            const int r = idx >> 4;
            const int c = (idx & 15) << 2;
            float4 k4 = *(const float4*)&kp[r * 64 + c];
            float4 v4 = *(const float4*)&vp[r * 64 + c];
            float* dk = &Ks[r * KST + c];
            float* dv = &Vs[r * VST + c];
            dk[0] = f2tf32f(k4.x); dk[1] = f2tf32f(k4.y);
            dk[2] = f2tf32f(k4.z); dk[3] = f2tf32f(k4.w);
            dv[0] = f2tf32f(v4.x); dv[1] = f2tf32f(v4.y);
            dv[2] = f2tf32f(v4.z); dv[3] = f2tf32f(v4.w);
        }
        __syncthreads();

        // ---- S = Q @ K^T : 8 n-tiles of 16x8, accumulate over 8 k-chunks.
        float SA[8][4];
#pragma unroll
        for (int nt = 0; nt < 8; ++nt)
#pragma unroll
            for (int j = 0; j < 4; ++j) SA[nt][j] = 0.f;

#pragma unroll
        for (int kt = 0; kt < 8; ++kt) {
#pragma unroll
            for (int nt = 0; nt < 8; ++nt) {
                uint32_t kb[2];
                const float* kr = &Ks[(nt * 8 + g) * KST + kt * 8 + t];
                kb[0] = __float_as_uint(kr[0]);
                kb[1] = __float_as_uint(kr[4]);
                mma_tf32(SA[nt], qf[kt], kb);
            }
        }

        // ---- Register softmax (rows g and g+8; this thread: cols nt*8+2t,+2t+1).
        float mr0 = SA[0][0], mr1 = SA[0][2];
#pragma unroll
        for (int nt = 0; nt < 8; ++nt) {
            mr0 = fmaxf(mr0, fmaxf(SA[nt][0], SA[nt][1]));
            mr1 = fmaxf(mr1, fmaxf(SA[nt][2], SA[nt][3]));
        }
        mr0 = fmaxf(mr0, __shfl_xor_sync(0xffffffffu, mr0, 1));
        mr0 = fmaxf(mr0, __shfl_xor_sync(0xffffffffu, mr0, 2));
        mr1 = fmaxf(mr1, __shfl_xor_sync(0xffffffffu, mr1, 1));
        mr1 = fmaxf(mr1, __shfl_xor_sync(0xffffffffu, mr1, 2));

        const float mnew0 = fmaxf(m0, mr0 * scale);
        const float mnew1 = fmaxf(m1, mr1 * scale);
        const float fac0  = __expf(m0 - mnew0);
        const float fac1  = __expf(m1 - mnew1);

        float sum0 = 0.f, sum1 = 0.f;
#pragma unroll
        for (int nt = 0; nt < 8; ++nt) {
            const float p00 = __expf(SA[nt][0] * scale - mnew0);
            const float p01 = __expf(SA[nt][1] * scale - mnew0);
            const float p10 = __expf(SA[nt][2] * scale - mnew1);
            const float p11 = __expf(SA[nt][3] * scale - mnew1);
            sum0 += p00 + p01;
            sum1 += p10 + p11;
            *(float2*)&patch[g * PST + nt * 8 + 2 * t] =
                make_float2(f2tf32f(p00), f2tf32f(p01));
            *(float2*)&patch[(g + 8) * PST + nt * 8 + 2 * t] =
                make_float2(f2tf32f(p10), f2tf32f(p11));
        }
        sum0 += __shfl_xor_sync(0xffffffffu, sum0, 1);
        sum0 += __shfl_xor_sync(0xffffffffu, sum0, 2);
        sum1 += __shfl_xor_sync(0xffffffffu, sum1, 1);
        sum1 += __shfl_xor_sync(0xffffffffu, sum1, 2);
        l0 = l0 * fac0 + sum0;
        l1 = l1 * fac1 + sum1;
        m0 = mnew0;
        m1 = mnew1;

        // ---- Rescale O in registers.
#pragma unroll
        for (int nt = 0; nt < 8; ++nt) {
            O[nt][0] *= fac0; O[nt][1] *= fac0;
            O[nt][2] *= fac1; O[nt][3] *= fac1;
        }
        __syncwarp();   // P patch visible warp-wide

        // ---- O += P @ V : 8 k-chunks (kv), 8 n-tiles (d).
#pragma unroll
        for (int kt = 0; kt < 8; ++kt) {
            uint32_t pa[4];
            pa[0] = __float_as_uint(patch[g * PST + kt * 8 + t]);
            pa[1] = __float_as_uint(patch[(g + 8) * PST + kt * 8 + t]);
            pa[2] = __float_as_uint(patch[g * PST + kt * 8 + t + 4]);
            pa[3] = __float_as_uint(patch[(g + 8) * PST + kt * 8 + t + 4]);
#pragma unroll
            for (int nt = 0; nt < 8; ++nt) {
                uint32_t vb[2];
                vb[0] = __float_as_uint(Vs[(kt * 8 + t) * VST + nt * 8 + g]);
                vb[1] = __float_as_uint(Vs[(kt * 8 + t + 4) * VST + nt * 8 + g]);
                mma_tf32(O[nt], pa, vb);
            }
        }
        __syncthreads();   // Ks/Vs free for next stage (also covers patch reuse)
    }

    // ---- Epilogue: rows g / g+8, cols nt*8 + {2t, 2t+1}.
    const int b = bh >> 4;
    const int h = bh & 15;
    const float inv0 = 1.f / l0;
    const float inv1 = 1.f / l1;
    const int r0 = qbase + wid * 16 + g;
    const int r1 = r0 + 8;
    float* o0 = &out[((size_t)(b * SEQ + r0)) * DIM + h * 64];
    float* o1 = &out[((size_t)(b * SEQ + r1)) * DIM + h * 64];
#pragma unroll
    for (int nt = 0; nt < 8; ++nt) {
        *(float2*)&o0[nt * 8 + 2 * t] = make_float2(O[nt][0] * inv0, O[nt][1] * inv0);
        *(float2*)&o1[nt * 8 + 2 * t] = make_float2(O[nt][2] * inv1, O[nt][3] * inv1);
    }
}

// ===========================================================================
extern "C" void kernel_launch(void* const* d_in, const int* in_sizes, int n_in,
                              void* d_out, int out_size)
{
    const float* q  = (const float*)d_in[0];
    const float* k  = (const float*)d_in[1];
    const float* v  = (const float*)d_in[2];
    const float* Wq = (const float*)d_in[3];
    const float* bq = (const float*)d_in[4];
    const float* Wk = (const float*)d_in[5];
    const float* bk = (const float*)d_in[6];
    const float* Wv = (const float*)d_in[7];
    const float* bv = (const float*)d_in[8];
    float* out = (float*)d_out;

    cudaFuncSetAttribute(attn_mma_kernel, cudaFuncAttributeMaxDynamicSharedMemorySize, ASMEM);

    dim3 pgrid(DIM / 128, (B_SZ * SEQ) / 128);       // (8, 64)
    proj_wmma_kernel<<<pgrid, 256>>>(q, Wq, bq, 0);
    proj_wmma_kernel<<<pgrid, 256>>>(k, Wk, bk, 1);
    proj_wmma_kernel<<<pgrid, 256>>>(v, Wv, bv, 2);

    dim3 agrid(SEQ / AQR, B_SZ * NUM_HEADS);         // (16, 64)
    attn_mma_kernel<<<agrid, 256, ASMEM>>>(out);
}

// round 10
// speedup vs baseline: 3.7079x; 1.5356x over previous
#include <cuda_runtime.h>
#include <cstdint>

#define NUM_HEADS 16
#define HEAD_DIM  64
#define B_SZ      4
#define SEQ       2048
#define DIM       1024

// Scratch for projected Q/K/V in [B, H, S, D] layout (no cudaMalloc allowed).
__device__ float g_Qp[B_SZ * SEQ * DIM];
__device__ float g_Kp[B_SZ * SEQ * DIM];
__device__ float g_Vp[B_SZ * SEQ * DIM];

__device__ __forceinline__ float f2tf32f(float x) {
    uint32_t u;
    asm("cvt.rna.tf32.f32 %0, %1;" : "=r"(u) : "f"(x));
    return __uint_as_float(u);
}
__device__ __forceinline__ uint32_t f2tf32u(float x) {
    uint32_t u;
    asm("cvt.rna.tf32.f32 %0, %1;" : "=r"(u) : "f"(x));
    return u;
}
__device__ __forceinline__ uint32_t smem_u32(const void* p) {
    uint32_t a;
    asm("{ .reg .u64 t; cvta.to.shared.u64 t, %1; cvt.u32.u64 %0, t; }" : "=r"(a) : "l"(p));
    return a;
}
__device__ __forceinline__ void cp16(uint32_t s, const void* g) {
    asm volatile("cp.async.ca.shared.global [%0], [%1], 16;" :: "r"(s), "l"(g));
}
#define CP_COMMIT() asm volatile("cp.async.commit_group;" ::: "memory")
#define CP_WAIT(n)  asm volatile("cp.async.wait_group %0;" :: "n"(n) : "memory")

// Raw tf32 MMA m16n8k8 (A row-major, B col-major), D/C fp32, accumulate in place.
__device__ __forceinline__ void mma_tf32(float d[4], const uint32_t a[4], const uint32_t b[2]) {
    asm volatile(
        "mma.sync.aligned.m16n8k8.row.col.f32.tf32.tf32.f32 "
        "{%0,%1,%2,%3}, {%4,%5,%6,%7}, {%8,%9}, {%0,%1,%2,%3};"
        : "+f"(d[0]), "+f"(d[1]), "+f"(d[2]), "+f"(d[3])
        : "r"(a[0]), "r"(a[1]), "r"(a[2]), "r"(a[3]), "r"(b[0]), "r"(b[1]));
}

// ===========================================================================
// Projection GEMM, raw mma.sync tf32, cp.async double-buffered.
//   C[8192,1024] = A @ W + bias (ReLU for which==2), scatter to [B,H,S,D].
// Block 128x128, BK=32, 256 thr / 8 warps (warpM 0..3 x warpN 0..1),
// warp = 32x64 out = 2 m-tiles x 8 n-tiles of m16n8k8. Operands staged as raw
// fp32 bits (tf32 MMA truncates mantissa in HW).
// ===========================================================================
#define PA_ST 36
#define PB_ST 136
#define PJ_ABUF (128 * PA_ST)
#define PJ_BBUF (32 * PB_ST)
#define PJ_SMEM ((2 * PJ_ABUF + 2 * PJ_BBUF) * 4)   // 71680 B

__global__ __launch_bounds__(256, 2) void proj_mma_kernel(
    const float* __restrict__ A, const float* __restrict__ W,
    const float* __restrict__ bias, int which)
{
    extern __shared__ float psm[];
    float* As = psm;                    // 2 x 128 x 36
    float* Bs = psm + 2 * PJ_ABUF;      // 2 x 32 x 136

    float* out = (which == 0) ? g_Qp : ((which == 1) ? g_Kp : g_Vp);
    const bool relu = (which == 2);

    const int tid  = threadIdx.x;
    const int wid  = tid >> 5;
    const int lane = tid & 31;
    const int g    = lane >> 2;
    const int t    = lane & 3;
    const int warpM = wid >> 1;
    const int warpN = wid & 1;
    const int rowBase = blockIdx.y * 128;
    const int colBase = blockIdx.x * 128;

    // staging indices (A: 128x32 = 1024 float4; B: 32x128 = 1024 float4)
    const int ar = tid >> 1;                 // with i-loop: r = (tid + i*256)>>3
    (void)ar;

    float acc[2][8][4];
#pragma unroll
    for (int mi = 0; mi < 2; mi++)
#pragma unroll
        for (int nt = 0; nt < 8; nt++)
#pragma unroll
            for (int j = 0; j < 4; j++) acc[mi][nt][j] = 0.f;

    const uint32_t asb = smem_u32(As);
    const uint32_t bsb = smem_u32(Bs);

    // ---- stage K-chunk k0 into buffer buf
    auto stage = [&](int buf, int k0) {
#pragma unroll
        for (int i = 0; i < 4; i++) {
            const int idx = tid + i * 256;
            const int r  = idx >> 3;
            const int c4 = (idx & 7) << 2;
            cp16(asb + (buf * PJ_ABUF + r * PA_ST + c4) * 4,
                 &A[(size_t)(rowBase + r) * DIM + k0 + c4]);
        }
#pragma unroll
        for (int i = 0; i < 4; i++) {
            const int idx = tid + i * 256;
            const int r  = idx >> 5;
            const int c4 = (idx & 31) << 2;
            cp16(bsb + (buf * PJ_BBUF + r * PB_ST + c4) * 4,
                 &W[(size_t)(k0 + r) * DIM + colBase + c4]);
        }
        CP_COMMIT();
    };

    stage(0, 0);

    const int m0 = warpM * 32;
    const int n0 = warpN * 64;

    for (int step = 0; step < DIM / 32; ++step) {
        const int buf = step & 1;
        if (step + 1 < DIM / 32) {
            stage(buf ^ 1, (step + 1) * 32);
            CP_WAIT(1);
        } else {
            CP_WAIT(0);
        }
        __syncthreads();

        const float* Ab = As + buf * PJ_ABUF;
        const float* Bb = Bs + buf * PJ_BBUF;

#pragma unroll
        for (int kk = 0; kk < 4; ++kk) {
            uint32_t af[2][4];
#pragma unroll
            for (int mi = 0; mi < 2; mi++) {
                const float* ar0 = &Ab[(m0 + mi * 16 + g) * PA_ST + kk * 8 + t];
                const float* ar1 = &Ab[(m0 + mi * 16 + g + 8) * PA_ST + kk * 8 + t];
                af[mi][0] = __float_as_uint(ar0[0]);
                af[mi][1] = __float_as_uint(ar1[0]);
                af[mi][2] = __float_as_uint(ar0[4]);
                af[mi][3] = __float_as_uint(ar1[4]);
            }
            uint32_t bf[8][2];
#pragma unroll
            for (int nt = 0; nt < 8; nt++) {
                bf[nt][0] = __float_as_uint(Bb[(kk * 8 + t) * PB_ST + n0 + nt * 8 + g]);
                bf[nt][1] = __float_as_uint(Bb[(kk * 8 + t + 4) * PB_ST + n0 + nt * 8 + g]);
            }
#pragma unroll
            for (int mi = 0; mi < 2; mi++)
#pragma unroll
                for (int nt = 0; nt < 8; nt++)
                    mma_tf32(acc[mi][nt], af[mi], bf[nt]);
        }
        __syncthreads();
    }

    // ---- Epilogue: bias + ReLU + scatter to [B,H,S,D]; float2 per (row,ntile).
    const int h = (colBase + n0) >> 6;
#pragma unroll
    for (int mi = 0; mi < 2; mi++) {
        const int mr0 = rowBase + m0 + mi * 16 + g;
        const int mr1 = mr0 + 8;
        const int bb0 = mr0 >> 11, s0 = mr0 & 2047;
        const int bb1 = mr1 >> 11, s1 = mr1 & 2047;
        float* o0 = &out[((((size_t)bb0 * NUM_HEADS + h) * SEQ + s0) << 6)];
        float* o1 = &out[((((size_t)bb1 * NUM_HEADS + h) * SEQ + s1) << 6)];
#pragma unroll
        for (int nt = 0; nt < 8; nt++) {
            const int n = colBase + n0 + nt * 8 + 2 * t;
            const int d = n & 63;
            const float bx = bias[n], by = bias[n + 1];
            float2 r0 = make_float2(acc[mi][nt][0] + bx, acc[mi][nt][1] + by);
            float2 r1 = make_float2(acc[mi][nt][2] + bx, acc[mi][nt][3] + by);
            if (relu) {
                r0.x = fmaxf(r0.x, 0.f); r0.y = fmaxf(r0.y, 0.f);
                r1.x = fmaxf(r1.x, 0.f); r1.y = fmaxf(r1.y, 0.f);
            }
            *(float2*)&o0[d] = r0;
            *(float2*)&o1[d] = r1;
        }
    }
}

// ===========================================================================
// Flash attention, register-resident raw mma.sync tf32 — unchanged (passing).
// ===========================================================================
#define KST 68
#define VST 72
#define PST 68
#define AQR 128
#define ASMEM ((64 * KST + 64 * VST + 8 * 16 * PST) * 4)

__global__ __launch_bounds__(256, 2) void attn_mma_kernel(float* __restrict__ out)
{
    extern __shared__ float sm[];
    float* Ks      = sm;
    float* Vs      = Ks + 64 * KST;
    float* Ppatch  = Vs + 64 * VST;

    const int tid  = threadIdx.x;
    const int wid  = tid >> 5;
    const int lane = tid & 31;
    const int g    = lane >> 2;
    const int t    = lane & 3;
    const int bh   = blockIdx.y;
    const int qbase = blockIdx.x * AQR;

    float* patch = Ppatch + wid * 16 * PST;

    const float* Qp = g_Qp + (size_t)bh * SEQ * 64 + (size_t)(qbase + wid * 16) * 64;
    const float* Kp = g_Kp + (size_t)bh * SEQ * 64;
    const float* Vp = g_Vp + (size_t)bh * SEQ * 64;

    uint32_t qf[8][4];
#pragma unroll
    for (int kt = 0; kt < 8; ++kt) {
        qf[kt][0] = f2tf32u(Qp[g * 64 + kt * 8 + t]);
        qf[kt][1] = f2tf32u(Qp[(g + 8) * 64 + kt * 8 + t]);
        qf[kt][2] = f2tf32u(Qp[g * 64 + kt * 8 + t + 4]);
        qf[kt][3] = f2tf32u(Qp[(g + 8) * 64 + kt * 8 + t + 4]);
    }

    float O[8][4];
#pragma unroll
    for (int nt = 0; nt < 8; ++nt)
#pragma unroll
        for (int j = 0; j < 4; ++j) O[nt][j] = 0.f;

    float m0 = -1e30f, m1 = -1e30f, l0 = 0.f, l1 = 0.f;
    const float scale = 0.125f;

    for (int kt_iter = 0; kt_iter < SEQ / 64; ++kt_iter) {
        const float* kp = Kp + (size_t)kt_iter * 64 * 64;
        const float* vp = Vp + (size_t)kt_iter * 64 * 64;

#pragma unroll
        for (int i = 0; i < 4; i++) {
            const int idx = tid + i * 256;
            const int r = idx >> 4;
            const int c = (idx & 15) << 2;
            float4 k4 = *(const float4*)&kp[r * 64 + c];
            float4 v4 = *(const float4*)&vp[r * 64 + c];
            float* dk = &Ks[r * KST + c];
            float* dv = &Vs[r * VST + c];
            dk[0] = f2tf32f(k4.x); dk[1] = f2tf32f(k4.y);
            dk[2] = f2tf32f(k4.z); dk[3] = f2tf32f(k4.w);
            dv[0] = f2tf32f(v4.x); dv[1] = f2tf32f(v4.y);
            dv[2] = f2tf32f(v4.z); dv[3] = f2tf32f(v4.w);
        }
        __syncthreads();

        float SA[8][4];
#pragma unroll
        for (int nt = 0; nt < 8; ++nt)
#pragma unroll
            for (int j = 0; j < 4; ++j) SA[nt][j] = 0.f;

#pragma unroll
        for (int kt = 0; kt < 8; ++kt) {
#pragma unroll
            for (int nt = 0; nt < 8; ++nt) {
                uint32_t kb[2];
                const float* kr = &Ks[(nt * 8 + g) * KST + kt * 8 + t];
                kb[0] = __float_as_uint(kr[0]);
                kb[1] = __float_as_uint(kr[4]);
                mma_tf32(SA[nt], qf[kt], kb);
            }
        }

        float mr0 = SA[0][0], mr1 = SA[0][2];
#pragma unroll
        for (int nt = 0; nt < 8; ++nt) {
            mr0 = fmaxf(mr0, fmaxf(SA[nt][0], SA[nt][1]));
            mr1 = fmaxf(mr1, fmaxf(SA[nt][2], SA[nt][3]));
        }
        mr0 = fmaxf(mr0, __shfl_xor_sync(0xffffffffu, mr0, 1));
        mr0 = fmaxf(mr0, __shfl_xor_sync(0xffffffffu, mr0, 2));
        mr1 = fmaxf(mr1, __shfl_xor_sync(0xffffffffu, mr1, 1));
        mr1 = fmaxf(mr1, __shfl_xor_sync(0xffffffffu, mr1, 2));

        const float mnew0 = fmaxf(m0, mr0 * scale);
        const float mnew1 = fmaxf(m1, mr1 * scale);
        const float fac0  = __expf(m0 - mnew0);
        const float fac1  = __expf(m1 - mnew1);

        float sum0 = 0.f, sum1 = 0.f;
#pragma unroll
        for (int nt = 0; nt < 8; ++nt) {
            const float p00 = __expf(SA[nt][0] * scale - mnew0);
            const float p01 = __expf(SA[nt][1] * scale - mnew0);
            const float p10 = __expf(SA[nt][2] * scale - mnew1);
            const float p11 = __expf(SA[nt][3] * scale - mnew1);
            sum0 += p00 + p01;
            sum1 += p10 + p11;
            *(float2*)&patch[g * PST + nt * 8 + 2 * t] =
                make_float2(f2tf32f(p00), f2tf32f(p01));
            *(float2*)&patch[(g + 8) * PST + nt * 8 + 2 * t] =
                make_float2(f2tf32f(p10), f2tf32f(p11));
        }
        sum0 += __shfl_xor_sync(0xffffffffu, sum0, 1);
        sum0 += __shfl_xor_sync(0xffffffffu, sum0, 2);
        sum1 += __shfl_xor_sync(0xffffffffu, sum1, 1);
        sum1 += __shfl_xor_sync(0xffffffffu, sum1, 2);
        l0 = l0 * fac0 + sum0;
        l1 = l1 * fac1 + sum1;
        m0 = mnew0;
        m1 = mnew1;

#pragma unroll
        for (int nt = 0; nt < 8; ++nt) {
            O[nt][0] *= fac0; O[nt][1] *= fac0;
            O[nt][2] *= fac1; O[nt][3] *= fac1;
        }
        __syncwarp();

#pragma unroll
        for (int kt = 0; kt < 8; ++kt) {
            uint32_t pa[4];
            pa[0] = __float_as_uint(patch[g * PST + kt * 8 + t]);
            pa[1] = __float_as_uint(patch[(g + 8) * PST + kt * 8 + t]);
            pa[2] = __float_as_uint(patch[g * PST + kt * 8 + t + 4]);
            pa[3] = __float_as_uint(patch[(g + 8) * PST + kt * 8 + t + 4]);
#pragma unroll
            for (int nt = 0; nt < 8; ++nt) {
                uint32_t vb[2];
                vb[0] = __float_as_uint(Vs[(kt * 8 + t) * VST + nt * 8 + g]);
                vb[1] = __float_as_uint(Vs[(kt * 8 + t + 4) * VST + nt * 8 + g]);
                mma_tf32(O[nt], pa, vb);
            }
        }
        __syncthreads();
    }

    const int b = bh >> 4;
    const int h = bh & 15;
    const float inv0 = 1.f / l0;
    const float inv1 = 1.f / l1;
    const int r0 = qbase + wid * 16 + g;
    const int r1 = r0 + 8;
    float* o0 = &out[((size_t)(b * SEQ + r0)) * DIM + h * 64];
    float* o1 = &out[((size_t)(b * SEQ + r1)) * DIM + h * 64];
#pragma unroll
    for (int nt = 0; nt < 8; ++nt) {
        *(float2*)&o0[nt * 8 + 2 * t] = make_float2(O[nt][0] * inv0, O[nt][1] * inv0);
        *(float2*)&o1[nt * 8 + 2 * t] = make_float2(O[nt][2] * inv1, O[nt][3] * inv1);
    }
}

// ===========================================================================
extern "C" void kernel_launch(void* const* d_in, const int* in_sizes, int n_in,
                              void* d_out, int out_size)
{
    const float* q  = (const float*)d_in[0];
    const float* k  = (const float*)d_in[1];
    const float* v  = (const float*)d_in[2];
    const float* Wq = (const float*)d_in[3];
    const float* bq = (const float*)d_in[4];
    const float* Wk = (const float*)d_in[5];
    const float* bk = (const float*)d_in[6];
    const float* Wv = (const float*)d_in[7];
    const float* bv = (const float*)d_in[8];
    float* out = (float*)d_out;

    cudaFuncSetAttribute(proj_mma_kernel, cudaFuncAttributeMaxDynamicSharedMemorySize, PJ_SMEM);
    cudaFuncSetAttribute(attn_mma_kernel, cudaFuncAttributeMaxDynamicSharedMemorySize, ASMEM);

    dim3 pgrid(DIM / 128, (B_SZ * SEQ) / 128);       // (8, 64)
    proj_mma_kernel<<<pgrid, 256, PJ_SMEM>>>(q, Wq, bq, 0);
    proj_mma_kernel<<<pgrid, 256, PJ_SMEM>>>(k, Wk, bk, 1);
    proj_mma_kernel<<<pgrid, 256, PJ_SMEM>>>(v, Wv, bv, 2);

    dim3 agrid(SEQ / AQR, B_SZ * NUM_HEADS);         // (16, 64)
    attn_mma_kernel<<<agrid, 256, ASMEM>>>(out);
}